// round 4
// baseline (speedup 1.0000x reference)
#include <cuda_runtime.h>

// SlowNorm: per-irrep L2 norms.
// irreps: (256,1) (256,3) (128,5) (64,7)  -> DIM=2112 in, OUT=704 out per row.
// Input offsets (floats): d1 [0,256), d3 [256,1024), d5 [1024,1664), d7 [1664,2112).
// Output offsets: [0,256) |x| ; [256,512) d=3 ; [512,640) d=5 ; [640,704) d=7.
//
// 4 adjacent rows per CTA: one contiguous 33792B coalesced stage with 8
// front-batched LDG.128 per thread. The d=1 block is element-wise |x| with
// identical float4 alignment -> computed and stored directly during staging
// (no smem round trip, no barrier dependency). Remaining outputs computed
// from smem, stored as STG.128.

#define DIM      2112
#define OUT_DIM  704
#define THREADS  256
#define ROWS     4
#define F4_ROW   (DIM / 4)              // 528
#define F4_TOTAL (ROWS * F4_ROW)        // 2112
#define CHUNKS_PER_ROW 112              // output float4 chunks q in [64,176)
#define CHUNKS_TOTAL   (ROWS * CHUNKS_PER_ROW)  // 448

__device__ __forceinline__ float4 ldcs4(const float4* p) {
    float4 v;
    asm volatile("ld.global.cs.v4.f32 {%0,%1,%2,%3}, [%4];\n"
                 : "=f"(v.x), "=f"(v.y), "=f"(v.z), "=f"(v.w) : "l"(p));
    return v;
}
__device__ __forceinline__ void stcs4(float4* p, float4 v) {
    asm volatile("st.global.cs.v4.f32 [%0], {%1,%2,%3,%4};\n"
                 :: "l"(p), "f"(v.x), "f"(v.y), "f"(v.z), "f"(v.w));
}

__global__ __launch_bounds__(THREADS) void slownorm_kernel(
    const float* __restrict__ in, float* __restrict__ out)
{
    __shared__ float s[ROWS * DIM];     // 33792 B

    const int tid = threadIdx.x;
    const long long row0 = (long long)blockIdx.x * ROWS;
    const float4* __restrict__ src =
        reinterpret_cast<const float4*>(in + row0 * DIM);
    float4* __restrict__ dst4 =
        reinterpret_cast<float4*>(out + row0 * OUT_DIM);
    float4* s4 = reinterpret_cast<float4*>(s);

    // ---- Stage: 2112 float4 = 8 full strides + 64-thread tail ----
    float4 x[8];
    #pragma unroll
    for (int k = 0; k < 8; k++)
        x[k] = ldcs4(src + tid + k * THREADS);
    float4 xt;
    if (tid < F4_TOTAL - 8 * THREADS)   // tail: 64 elements
        xt = ldcs4(src + 8 * THREADS + tid);

    #pragma unroll
    for (int k = 0; k < 8; k++) {
        const int i = tid + k * THREADS;
        const int r = i / F4_ROW;
        const int w = i - r * F4_ROW;
        if (w < 64) {
            // d=1 block: |x| straight to output (chunk q == w).
            float4 v;
            v.x = fabsf(x[k].x); v.y = fabsf(x[k].y);
            v.z = fabsf(x[k].z); v.w = fabsf(x[k].w);
            stcs4(dst4 + r * (OUT_DIM / 4) + w, v);
        } else {
            s4[i] = x[k];
        }
    }
    if (tid < F4_TOTAL - 8 * THREADS) {
        const int i = 8 * THREADS + tid;        // 2048..2111 -> row 3, w 464..527
        s4[i] = xt;
    }
    __syncthreads();

    // ---- Compute: 448 non-scalar chunks (q in [64,176) per row) ----
    #pragma unroll
    for (int c = tid; c < CHUNKS_TOTAL; c += THREADS) {
        const int r = c / CHUNKS_PER_ROW;
        const int q = 64 + (c - r * CHUNKS_PER_ROW);
        const float* __restrict__ b = s + r * DIM;
        float a[4];
        if (q < 128) {                          // d=3
            const int p = 256 + (4 * q - 256) * 3;
            #pragma unroll
            for (int k = 0; k < 4; k++) {
                const float* e = b + p + 3 * k;
                float acc = e[0] * e[0];
                acc = fmaf(e[1], e[1], acc);
                acc = fmaf(e[2], e[2], acc);
                a[k] = sqrtf(acc);
            }
        } else if (q < 160) {                   // d=5
            const int p = 1024 + (4 * q - 512) * 5;
            #pragma unroll
            for (int k = 0; k < 4; k++) {
                const float* e = b + p + 5 * k;
                float acc = e[0] * e[0];
                #pragma unroll
                for (int j = 1; j < 5; j++) acc = fmaf(e[j], e[j], acc);
                a[k] = sqrtf(acc);
            }
        } else {                                // d=7
            const int p = 1664 + (4 * q - 640) * 7;
            #pragma unroll
            for (int k = 0; k < 4; k++) {
                const float* e = b + p + 7 * k;
                float acc = e[0] * e[0];
                #pragma unroll
                for (int j = 1; j < 7; j++) acc = fmaf(e[j], e[j], acc);
                a[k] = sqrtf(acc);
            }
        }
        float4 v; v.x = a[0]; v.y = a[1]; v.z = a[2]; v.w = a[3];
        stcs4(dst4 + r * (OUT_DIM / 4) + q, v);
    }
}

extern "C" void kernel_launch(void* const* d_in, const int* in_sizes, int n_in,
                              void* d_out, int out_size)
{
    const float* features = (const float*)d_in[0];
    float* out = (float*)d_out;
    const int batch = in_sizes[0] / DIM;       // 65536 (divisible by 4)
    slownorm_kernel<<<batch / ROWS, THREADS>>>(features, out);
}

// round 5
// speedup vs baseline: 1.0939x; 1.0939x over previous
#include <cuda_runtime.h>

// SlowNorm: per-irrep L2 norms.
// irreps: (256,1) (256,3) (128,5) (64,7)  -> DIM=2112 in, OUT=704 out per row.
// Input offsets (floats): d1 [0,256), d3 [256,1024), d5 [1024,1664), d7 [1664,2112).
// Output offsets: [0,256) |x| ; [256,512) d=3 ; [512,640) d=5 ; [640,704) d=7.
//
// R3 shape (2 rows/CTA, 17KB smem -> high occupancy) + d=1 bypass:
// the scalar block is |x| with identical float4 alignment, so it's computed
// and stored directly in the staging loop (no smem round trip, drains early).
// Remaining 224 output chunks fit in one non-looped pass over 256 threads.

#define DIM      2112
#define OUT_DIM  704
#define THREADS  256
#define ROWS     2
#define F4_ROW   (DIM / 4)               // 528
#define F4_TOTAL (ROWS * F4_ROW)         // 1056 = 4*256 + 32
#define CHUNKS_PER_ROW 112               // q in [64,176)
#define CHUNKS_TOTAL   (ROWS * CHUNKS_PER_ROW)  // 224 (< THREADS)

__device__ __forceinline__ float4 ldcs4(const float4* p) {
    float4 v;
    asm volatile("ld.global.cs.v4.f32 {%0,%1,%2,%3}, [%4];\n"
                 : "=f"(v.x), "=f"(v.y), "=f"(v.z), "=f"(v.w) : "l"(p));
    return v;
}
__device__ __forceinline__ void stcs4(float4* p, float4 v) {
    asm volatile("st.global.cs.v4.f32 [%0], {%1,%2,%3,%4};\n"
                 :: "l"(p), "f"(v.x), "f"(v.y), "f"(v.z), "f"(v.w));
}

__global__ __launch_bounds__(THREADS) void slownorm_kernel(
    const float* __restrict__ in, float* __restrict__ out)
{
    __shared__ float s[ROWS * DIM];      // 16896 B

    const int tid = threadIdx.x;
    const long long row0 = (long long)blockIdx.x * ROWS;
    const float4* __restrict__ src =
        reinterpret_cast<const float4*>(in + row0 * DIM);
    float4* __restrict__ dst4 =
        reinterpret_cast<float4*>(out + row0 * OUT_DIM);
    float4* s4 = reinterpret_cast<float4*>(s);

    // ---- Stage: 1056 float4 = 4 full strides + 32-thread tail ----
    float4 x[4];
    #pragma unroll
    for (int k = 0; k < 4; k++)
        x[k] = ldcs4(src + tid + k * THREADS);
    float4 xt;
    if (tid < F4_TOTAL - 4 * THREADS)    // tail: 32 float4 (row 1, w 496..527)
        xt = ldcs4(src + 4 * THREADS + tid);

    #pragma unroll
    for (int k = 0; k < 4; k++) {
        const int i = tid + k * THREADS;
        const int r = i / F4_ROW;
        const int w = i - r * F4_ROW;
        if (w < 64) {
            // d=1: |x| straight to output (output chunk q == w).
            float4 v;
            v.x = fabsf(x[k].x); v.y = fabsf(x[k].y);
            v.z = fabsf(x[k].z); v.w = fabsf(x[k].w);
            stcs4(dst4 + r * (OUT_DIM / 4) + w, v);
        } else {
            s4[i] = x[k];
        }
    }
    if (tid < F4_TOTAL - 4 * THREADS)
        s4[4 * THREADS + tid] = xt;      // tail is all w>=64 (row 1)
    __syncthreads();

    // ---- Compute: 224 chunks, one per thread (tid < 224) ----
    if (tid < CHUNKS_TOTAL) {
        const int r = tid / CHUNKS_PER_ROW;
        const int q = 64 + (tid - r * CHUNKS_PER_ROW);
        const float* __restrict__ b = s + r * DIM;
        float a[4];
        if (q < 128) {                           // d=3
            const int p = 256 + (4 * q - 256) * 3;
            #pragma unroll
            for (int k = 0; k < 4; k++) {
                const float* e = b + p + 3 * k;
                float acc = e[0] * e[0];
                acc = fmaf(e[1], e[1], acc);
                acc = fmaf(e[2], e[2], acc);
                a[k] = sqrtf(acc);
            }
        } else if (q < 160) {                    // d=5
            const int p = 1024 + (4 * q - 512) * 5;
            #pragma unroll
            for (int k = 0; k < 4; k++) {
                const float* e = b + p + 5 * k;
                float acc = e[0] * e[0];
                #pragma unroll
                for (int j = 1; j < 5; j++) acc = fmaf(e[j], e[j], acc);
                a[k] = sqrtf(acc);
            }
        } else {                                 // d=7
            const int p = 1664 + (4 * q - 640) * 7;
            #pragma unroll
            for (int k = 0; k < 4; k++) {
                const float* e = b + p + 7 * k;
                float acc = e[0] * e[0];
                #pragma unroll
                for (int j = 1; j < 7; j++) acc = fmaf(e[j], e[j], acc);
                a[k] = sqrtf(acc);
            }
        }
        float4 v; v.x = a[0]; v.y = a[1]; v.z = a[2]; v.w = a[3];
        stcs4(dst4 + r * (OUT_DIM / 4) + q, v);
    }
}

extern "C" void kernel_launch(void* const* d_in, const int* in_sizes, int n_in,
                              void* d_out, int out_size)
{
    const float* features = (const float*)d_in[0];
    float* out = (float*)d_out;
    const int batch = in_sizes[0] / DIM;        // 65536 (even)
    slownorm_kernel<<<batch / ROWS, THREADS>>>(features, out);
}